// round 3
// baseline (speedup 1.0000x reference)
#include <cuda_runtime.h>
#include <math.h>

#define Bb 64
#define Tt 1024
#define Ii 64
#define Hh 512
#define G3 1536
#define BT (Bb*Tt)
#define NBLK 384

// ---------------- scratch (static device allocations only) ----------------
__device__ float g_xg[(size_t)BT * G3];      // [B*T, 3H] input-side gates (reused per layer)
__device__ float g_y[(size_t)BT * Hh];       // [B*T, H] layer output (reused)
__device__ float g_h[2 * Bb * Hh];           // ping-pong hidden state
__device__ float g_part[4 * Bb * G3];        // split-K partials [ks][B][3H]
__device__ float g_wih0T[Ii * G3];
__device__ float g_whh0T[Hh * G3];
__device__ float g_wih1T[Hh * G3];
__device__ float g_whh1T[Hh * G3];
__device__ float g_fcwT[Hh * Ii];

__device__ unsigned int g_arrive;
__device__ unsigned int g_gen;

// ---------------- transpose: in[R][C] -> out[C][R] ----------------
__global__ void transpose_k(const float* __restrict__ in, float* __restrict__ out,
                            int R, int C) {
    __shared__ float tile[32][33];
    int c0 = blockIdx.x * 32, r0 = blockIdx.y * 32;
    int x = threadIdx.x, y = threadIdx.y;
#pragma unroll
    for (int j = 0; j < 32; j += 8)
        tile[y + j][x] = in[(size_t)(r0 + y + j) * C + c0 + x];
    __syncthreads();
#pragma unroll
    for (int j = 0; j < 32; j += 8)
        out[(size_t)(c0 + y + j) * R + r0 + x] = tile[x][y + j];
}

// ---------------- generic tiled GEMM: out[M][N] = X[M][K] @ Wt[K][N] + bias ----------------
__global__ void gemm_bias(const float* __restrict__ X, const float* __restrict__ Wt,
                          const float* __restrict__ bias, float* __restrict__ out,
                          int M, int K, int N) {
    __shared__ float As[16][64];   // [k][m]
    __shared__ float Bs[16][64];   // [k][n]
    int tid = threadIdx.x;
    int n0 = blockIdx.x * 64, m0 = blockIdx.y * 64;
    int tx = tid % 16, ty = tid / 16;
    int am = tid / 4, ak = (tid % 4) * 4;     // A loader: row am, 4 k's
    int bk = tid / 16, bn = (tid % 16) * 4;   // B loader
    float acc[4][4];
#pragma unroll
    for (int i = 0; i < 4; i++)
#pragma unroll
        for (int j = 0; j < 4; j++) acc[i][j] = 0.f;

    for (int k0 = 0; k0 < K; k0 += 16) {
        float4 av = *(const float4*)&X[(size_t)(m0 + am) * K + k0 + ak];
        As[ak + 0][am] = av.x; As[ak + 1][am] = av.y;
        As[ak + 2][am] = av.z; As[ak + 3][am] = av.w;
        *(float4*)&Bs[bk][bn] = *(const float4*)&Wt[(size_t)(k0 + bk) * N + n0 + bn];
        __syncthreads();
#pragma unroll
        for (int k = 0; k < 16; k++) {
            float4 a = *(const float4*)&As[k][ty * 4];
            float4 b = *(const float4*)&Bs[k][tx * 4];
            acc[0][0] += a.x * b.x; acc[0][1] += a.x * b.y; acc[0][2] += a.x * b.z; acc[0][3] += a.x * b.w;
            acc[1][0] += a.y * b.x; acc[1][1] += a.y * b.y; acc[1][2] += a.y * b.z; acc[1][3] += a.y * b.w;
            acc[2][0] += a.z * b.x; acc[2][1] += a.z * b.y; acc[2][2] += a.z * b.z; acc[2][3] += a.z * b.w;
            acc[3][0] += a.w * b.x; acc[3][1] += a.w * b.y; acc[3][2] += a.w * b.z; acc[3][3] += a.w * b.w;
        }
        __syncthreads();
    }
    float4 bv = *(const float4*)&bias[n0 + tx * 4];
#pragma unroll
    for (int i = 0; i < 4; i++) {
        float4 o;
        o.x = acc[i][0] + bv.x; o.y = acc[i][1] + bv.y;
        o.z = acc[i][2] + bv.z; o.w = acc[i][3] + bv.w;
        *(float4*)&out[(size_t)(m0 + ty * 4 + i) * N + n0 + tx * 4] = o;
    }
}

// ---------------- grid barrier (software, co-resident grid) ----------------
__global__ void bar_reset() { g_arrive = 0u; g_gen = 0u; }

__device__ __forceinline__ void grid_barrier(unsigned int target) {
    __syncthreads();
    if (threadIdx.x == 0) {
        __threadfence();
        unsigned int a = atomicAdd(&g_arrive, 1u);
        if (a == NBLK - 1) {
            g_arrive = 0u;
            __threadfence();
            atomicExch(&g_gen, target);
        } else {
            while (*((volatile unsigned int*)&g_gen) < target) {}
            __threadfence();
        }
    }
    __syncthreads();
}

// ---------------- persistent recurrent layer ----------------
// 384 blocks x 256 threads. Block (gt 0..23, bt 0..3, kz 0..3):
// phase 1: partial hg for [gt*64 .. +64) x [bt*16 .. +16) over K slice [kz*128 .. +128)
// phase 2: blocks 0..127 do the fused gate update (32768 elements)
__global__ void __launch_bounds__(256, 4)
gru_layer_persistent(const float* __restrict__ xg, const float* __restrict__ whhT,
                     const float* __restrict__ bhh, float* __restrict__ h,
                     float* __restrict__ part, float* __restrict__ y) {
    const int tid = threadIdx.x;
    const int bid = blockIdx.x;
    const int gt = (bid % 24) * 64;
    const int bt = ((bid / 24) % 4) * 16;
    const int kz = bid / 96;
    const int k0 = kz * 128;
    const int tx = tid % 16, ty = tid / 16;
    const int hb = tid / 16, hk = tid % 16;
    const int BH = Bb * Hh;

    __shared__ float hs[16][17];   // [k][b]
    __shared__ float ws[16][64];   // [k][g]

    unsigned int bar = 0;

    // zero h ping-pong cooperatively
    for (int i = bid * 256 + tid; i < 2 * BH; i += NBLK * 256) h[i] = 0.f;
    grid_barrier(++bar);

    for (int t = 0; t < Tt; t++) {
        const float* hi = h + (t & 1) * BH;
        float* ho = h + ((t + 1) & 1) * BH;

        // ---- phase 1: partial hg ----
        float a0 = 0.f, a1 = 0.f, a2 = 0.f, a3 = 0.f;
        for (int kc = 0; kc < 128; kc += 16) {
            hs[hk][hb] = hi[(size_t)(bt + hb) * Hh + k0 + kc + hk];
#pragma unroll
            for (int u = 0; u < 4; u++) {
                int i = tid + u * 256;
                ws[i >> 6][i & 63] = whhT[(size_t)(k0 + kc + (i >> 6)) * G3 + gt + (i & 63)];
            }
            __syncthreads();
#pragma unroll
            for (int k = 0; k < 16; k++) {
                float4 wv = *(const float4*)&ws[k][tx * 4];
                float hv = hs[k][ty];
                a0 += hv * wv.x; a1 += hv * wv.y; a2 += hv * wv.z; a3 += hv * wv.w;
            }
            __syncthreads();
        }
        {
            size_t o = ((size_t)kz * Bb + bt + ty) * G3 + gt + tx * 4;
            *(float4*)&part[o] = make_float4(a0, a1, a2, a3);
        }
        grid_barrier(++bar);

        // ---- phase 2: fused gate update (first 128 blocks) ----
        int idx = bid * 256 + tid;
        if (idx < BH) {
            int b = idx >> 9, j = idx & 511;
            float hr = bhh[j], hz = bhh[Hh + j], hn = bhh[2 * Hh + j];
#pragma unroll
            for (int ks = 0; ks < 4; ks++) {
                const float* p = part + ((size_t)ks * Bb + b) * G3;
                hr += p[j]; hz += p[Hh + j]; hn += p[2 * Hh + j];
            }
            const float* xp = xg + ((size_t)b * Tt + t) * G3 + j;
            float r = 1.f / (1.f + expf(-(xp[0] + hr)));
            float z = 1.f / (1.f + expf(-(xp[Hh] + hz)));
            float n = tanhf(xp[2 * Hh] + r * hn);
            float hp = hi[b * Hh + j];
            float v = (1.f - z) * n + z * hp;
            ho[b * Hh + j] = v;
            y[((size_t)b * Tt + t) * Hh + j] = v;
        }
        grid_barrier(++bar);
    }
}

// ---------------- launch ----------------
extern "C" void kernel_launch(void* const* d_in, const int* in_sizes, int n_in,
                              void* d_out, int out_size) {
    const float* x     = (const float*)d_in[0];
    const float* w_ih0 = (const float*)d_in[1];
    const float* w_hh0 = (const float*)d_in[2];
    const float* b_ih0 = (const float*)d_in[3];
    const float* b_hh0 = (const float*)d_in[4];
    const float* w_ih1 = (const float*)d_in[5];
    const float* w_hh1 = (const float*)d_in[6];
    const float* b_ih1 = (const float*)d_in[7];
    const float* b_hh1 = (const float*)d_in[8];
    const float* fc_w  = (const float*)d_in[9];
    const float* fc_b  = (const float*)d_in[10];
    float* out = (float*)d_out;

    float *xg, *y, *h, *part, *wih0T, *whh0T, *wih1T, *whh1T, *fcwT;
    cudaGetSymbolAddress((void**)&xg,    g_xg);
    cudaGetSymbolAddress((void**)&y,     g_y);
    cudaGetSymbolAddress((void**)&h,     g_h);
    cudaGetSymbolAddress((void**)&part,  g_part);
    cudaGetSymbolAddress((void**)&wih0T, g_wih0T);
    cudaGetSymbolAddress((void**)&whh0T, g_whh0T);
    cudaGetSymbolAddress((void**)&wih1T, g_wih1T);
    cudaGetSymbolAddress((void**)&whh1T, g_whh1T);
    cudaGetSymbolAddress((void**)&fcwT,  g_fcwT);

    dim3 tb(32, 8);
    transpose_k<<<dim3(Ii / 32, G3 / 32), tb>>>(w_ih0, wih0T, G3, Ii);
    transpose_k<<<dim3(Hh / 32, G3 / 32), tb>>>(w_hh0, whh0T, G3, Hh);
    transpose_k<<<dim3(Hh / 32, G3 / 32), tb>>>(w_ih1, wih1T, G3, Hh);
    transpose_k<<<dim3(Hh / 32, G3 / 32), tb>>>(w_hh1, whh1T, G3, Hh);
    transpose_k<<<dim3(Hh / 32, Ii / 32), tb>>>(fc_w,  fcwT,  Ii, Hh);

    // -------- layer 0 --------
    gemm_bias<<<dim3(G3 / 64, BT / 64), 256>>>(x, wih0T, b_ih0, xg, BT, Ii, G3);
    bar_reset<<<1, 1>>>();
    gru_layer_persistent<<<NBLK, 256>>>(xg, whh0T, b_hh0, h, part, y);

    // -------- layer 1 --------
    gemm_bias<<<dim3(G3 / 64, BT / 64), 256>>>(y, wih1T, b_ih1, xg, BT, Hh, G3);
    bar_reset<<<1, 1>>>();
    gru_layer_persistent<<<NBLK, 256>>>(xg, whh1T, b_hh1, h, part, y);

    // -------- final FC --------
    gemm_bias<<<dim3(Ii / 64, BT / 64), 256>>>(y, fcwT, fc_b, out, BT, Hh, Ii);
}

// round 4
// speedup vs baseline: 2.0353x; 2.0353x over previous
#include <cuda_runtime.h>
#include <math.h>

#define Bb 64
#define Tt 1024
#define Ii 64
#define Hh 512
#define G3 1536
#define BT (Bb*Tt)
#define NBLK 128
#define NTHR 512

// SMEM layout (floats): h_s[512*64] | w_s[512*16] | part_s[8*64*12]
#define SM_HS   (Hh * Bb)
#define SM_WS   (Hh * 16)
#define SM_PART (8 * 64 * 12)
#define SMEM_BYTES ((SM_HS + SM_WS + SM_PART) * 4)

// ---------------- scratch (static device allocations only) ----------------
__device__ float g_xg[(size_t)BT * G3];      // [B*T, 3H]
__device__ float g_y[(size_t)BT * Hh];       // [B*T, H]
__device__ float g_hT[2 * Hh * Bb];          // ping-pong hidden, TRANSPOSED [H][B]
__device__ float g_wih0T[Ii * G3];
__device__ float g_wih1T[Hh * G3];
__device__ float g_fcwT[Hh * Ii];
__device__ unsigned int g_arrive;
__device__ unsigned int g_gen;

// ---------------- transpose: in[R][C] -> out[C][R] ----------------
__global__ void transpose_k(const float* __restrict__ in, float* __restrict__ out,
                            int R, int C) {
    __shared__ float tile[32][33];
    int c0 = blockIdx.x * 32, r0 = blockIdx.y * 32;
    int x = threadIdx.x, y = threadIdx.y;
#pragma unroll
    for (int j = 0; j < 32; j += 8)
        tile[y + j][x] = in[(size_t)(r0 + y + j) * C + c0 + x];
    __syncthreads();
#pragma unroll
    for (int j = 0; j < 32; j += 8)
        out[(size_t)(c0 + y + j) * R + r0 + x] = tile[x][y + j];
}

// ---------------- tiled GEMM: out[M][N] = X[M][K] @ Wt[K][N] + bias ----------------
__global__ void gemm_bias(const float* __restrict__ X, const float* __restrict__ Wt,
                          const float* __restrict__ bias, float* __restrict__ out,
                          int M, int K, int N) {
    __shared__ float As[16][64];
    __shared__ float Bs[16][64];
    int tid = threadIdx.x;
    int n0 = blockIdx.x * 64, m0 = blockIdx.y * 64;
    int tx = tid % 16, ty = tid / 16;
    int am = tid / 4, ak = (tid % 4) * 4;
    int bk = tid / 16, bn = (tid % 16) * 4;
    float acc[4][4];
#pragma unroll
    for (int i = 0; i < 4; i++)
#pragma unroll
        for (int j = 0; j < 4; j++) acc[i][j] = 0.f;

    for (int k0 = 0; k0 < K; k0 += 16) {
        float4 av = *(const float4*)&X[(size_t)(m0 + am) * K + k0 + ak];
        As[ak + 0][am] = av.x; As[ak + 1][am] = av.y;
        As[ak + 2][am] = av.z; As[ak + 3][am] = av.w;
        *(float4*)&Bs[bk][bn] = *(const float4*)&Wt[(size_t)(k0 + bk) * N + n0 + bn];
        __syncthreads();
#pragma unroll
        for (int k = 0; k < 16; k++) {
            float4 a = *(const float4*)&As[k][ty * 4];
            float4 b = *(const float4*)&Bs[k][tx * 4];
            acc[0][0] += a.x * b.x; acc[0][1] += a.x * b.y; acc[0][2] += a.x * b.z; acc[0][3] += a.x * b.w;
            acc[1][0] += a.y * b.x; acc[1][1] += a.y * b.y; acc[1][2] += a.y * b.z; acc[1][3] += a.y * b.w;
            acc[2][0] += a.z * b.x; acc[2][1] += a.z * b.y; acc[2][2] += a.z * b.z; acc[2][3] += a.z * b.w;
            acc[3][0] += a.w * b.x; acc[3][1] += a.w * b.y; acc[3][2] += a.w * b.z; acc[3][3] += a.w * b.w;
        }
        __syncthreads();
    }
    float4 bv = *(const float4*)&bias[n0 + tx * 4];
#pragma unroll
    for (int i = 0; i < 4; i++) {
        float4 o;
        o.x = acc[i][0] + bv.x; o.y = acc[i][1] + bv.y;
        o.z = acc[i][2] + bv.z; o.w = acc[i][3] + bv.w;
        *(float4*)&out[(size_t)(m0 + ty * 4 + i) * N + n0 + tx * 4] = o;
    }
}

// ---------------- grid barrier ----------------
__global__ void bar_reset() { g_arrive = 0u; g_gen = 0u; }

__device__ __forceinline__ void grid_barrier(unsigned int target) {
    __syncthreads();
    if (threadIdx.x == 0) {
        __threadfence();
        unsigned int a = atomicAdd(&g_arrive, 1u);
        if (a == NBLK - 1) {
            g_arrive = 0u;
            __threadfence();
            atomicExch(&g_gen, target);
        } else {
            while (*((volatile unsigned int*)&g_gen) < target) {}
            __threadfence();
        }
    }
    __syncthreads();
}

// ---------------- weight-stationary persistent GRU layer ----------------
// 128 blocks x 512 threads, 1 block/SM. Block bid owns h-cols j0..j0+3
// (gate cols j0+j, 512+j0+j, 1024+j0+j). whh raw layout [3H][H].
__global__ void __launch_bounds__(NTHR, 1)
gru_layer_ws(const float* __restrict__ xg, const float* __restrict__ whh,
             const float* __restrict__ bhh, float* __restrict__ hT,
             float* __restrict__ y) {
    extern __shared__ float smem[];
    float* h_s    = smem;                 // [k][b] stride 64
    float* w_s    = smem + SM_HS;         // [k][j][g(4)] stride 16, g3 = pad
    float* part_s = smem + SM_HS + SM_WS; // [kc][out][3 gates][4 b]

    const int tid = threadIdx.x;
    const int bid = blockIdx.x;
    const int j0 = bid * 4;
    const int out_tid = tid & 63;   // 0..63
    const int kc = tid >> 6;        // 0..7
    const int bg = out_tid >> 2;    // 0..15 (b0 = bg*4)
    const int jj = out_tid & 3;     // 0..3
    const int BH = Bb * Hh;

    // ---- one-time: load W_hh slice into SMEM (12 rows of 512) ----
    for (int idx = tid; idx < 12 * Hh; idx += NTHR) {
        int row = idx >> 9;            // 0..11
        int k = idx & 511;
        int j = row & 3, g = row >> 2; // g 0..2
        w_s[k * 16 + j * 4 + g] = whh[(size_t)(g * Hh + j0 + j) * Hh + k];
    }
    // zero h ping-pong
    for (int i = bid * NTHR + tid; i < 2 * BH; i += NBLK * NTHR) hT[i] = 0.f;

    unsigned int bar = 0;
    grid_barrier(++bar);

    float4* hs4 = (float4*)h_s;
    const float4* ws4 = (const float4*)w_s;

    for (int t = 0; t < Tt; t++) {
        const float* hcur = hT + (t & 1) * BH;
        float* hnext = hT + ((t + 1) & 1) * BH;

        // prefetch xg for gate update (DRAM; hidden under staging+GEMM)
        float xr = 0.f, xz = 0.f, xn = 0.f;
        if (tid < 256) {
            int b = tid >> 2, j = tid & 3;
            const float* xp = xg + ((size_t)b * Tt + t) * G3 + j0 + j;
            xr = xp[0]; xz = xp[Hh]; xn = xp[2 * Hh];
        }

        // ---- stage full h into SMEM (coalesced float4 copy, [k][b]) ----
        const float4* hc4 = (const float4*)hcur;
#pragma unroll
        for (int i = 0; i < 16; i++)
            hs4[tid + i * NTHR] = hc4[tid + i * NTHR];
        __syncthreads();

        // ---- GEMM partials: this thread: 4 b's (bg*4..+3), col j0+jj, k slice kc ----
        float4 ar = make_float4(0.f, 0.f, 0.f, 0.f);
        float4 az = make_float4(0.f, 0.f, 0.f, 0.f);
        float4 an = make_float4(0.f, 0.f, 0.f, 0.f);
        int kbase = kc * 64;
#pragma unroll 4
        for (int k = kbase; k < kbase + 64; k++) {
            float4 hv = hs4[k * 16 + bg];
            float4 wv = ws4[k * 4 + jj];
            ar.x += hv.x * wv.x; ar.y += hv.y * wv.x; ar.z += hv.z * wv.x; ar.w += hv.w * wv.x;
            az.x += hv.x * wv.y; az.y += hv.y * wv.y; az.z += hv.z * wv.y; az.w += hv.w * wv.y;
            an.x += hv.x * wv.z; an.y += hv.y * wv.z; an.z += hv.z * wv.z; an.w += hv.w * wv.z;
        }
        {
            float4* p4 = (float4*)part_s;
            int pb = (kc * 64 + out_tid) * 3;
            p4[pb + 0] = ar; p4[pb + 1] = az; p4[pb + 2] = an;
        }
        __syncthreads();

        // ---- reduce + gate update: threads 0..255 handle (b, j) ----
        if (tid < 256) {
            int b = tid >> 2, j = tid & 3;
            int out = ((b >> 2) << 2) + j;   // matches producer out_tid
            int c = b & 3;                   // lane within float4
            float hr = bhh[j0 + j], hz = bhh[Hh + j0 + j], hn = bhh[2 * Hh + j0 + j];
#pragma unroll
            for (int q = 0; q < 8; q++) {
                int base = ((q * 64 + out) * 3) * 4 + c;
                hr += part_s[base];
                hz += part_s[base + 4];
                hn += part_s[base + 8];
            }
            float r = 1.f / (1.f + expf(-(xr + hr)));
            float z = 1.f / (1.f + expf(-(xz + hz)));
            float n = tanhf(xn + r * hn);
            float hp = h_s[(j0 + j) * Bb + b];       // h_cur from SMEM
            float v = (1.f - z) * n + z * hp;
            hnext[(j0 + j) * Bb + b] = v;
            y[((size_t)b * Tt + t) * Hh + j0 + j] = v;
        }
        grid_barrier(++bar);
    }
}

// ---------------- launch ----------------
extern "C" void kernel_launch(void* const* d_in, const int* in_sizes, int n_in,
                              void* d_out, int out_size) {
    const float* x     = (const float*)d_in[0];
    const float* w_ih0 = (const float*)d_in[1];
    const float* w_hh0 = (const float*)d_in[2];
    const float* b_ih0 = (const float*)d_in[3];
    const float* b_hh0 = (const float*)d_in[4];
    const float* w_ih1 = (const float*)d_in[5];
    const float* w_hh1 = (const float*)d_in[6];
    const float* b_ih1 = (const float*)d_in[7];
    const float* b_hh1 = (const float*)d_in[8];
    const float* fc_w  = (const float*)d_in[9];
    const float* fc_b  = (const float*)d_in[10];
    float* out = (float*)d_out;

    float *xg, *y, *hT, *wih0T, *wih1T, *fcwT;
    cudaGetSymbolAddress((void**)&xg,    g_xg);
    cudaGetSymbolAddress((void**)&y,     g_y);
    cudaGetSymbolAddress((void**)&hT,    g_hT);
    cudaGetSymbolAddress((void**)&wih0T, g_wih0T);
    cudaGetSymbolAddress((void**)&wih1T, g_wih1T);
    cudaGetSymbolAddress((void**)&fcwT,  g_fcwT);

    cudaFuncSetAttribute(gru_layer_ws,
                         cudaFuncAttributeMaxDynamicSharedMemorySize, SMEM_BYTES);

    dim3 tb(32, 8);
    transpose_k<<<dim3(Ii / 32, G3 / 32), tb>>>(w_ih0, wih0T, G3, Ii);
    transpose_k<<<dim3(Hh / 32, G3 / 32), tb>>>(w_ih1, wih1T, G3, Hh);
    transpose_k<<<dim3(Hh / 32, Ii / 32), tb>>>(fc_w,  fcwT,  Ii, Hh);

    // -------- layer 0 --------
    gemm_bias<<<dim3(G3 / 64, BT / 64), 256>>>(x, wih0T, b_ih0, xg, BT, Ii, G3);
    bar_reset<<<1, 1>>>();
    gru_layer_ws<<<NBLK, NTHR, SMEM_BYTES>>>(xg, w_hh0, b_hh0, hT, y);

    // -------- layer 1 --------
    gemm_bias<<<dim3(G3 / 64, BT / 64), 256>>>(y, wih1T, b_ih1, xg, BT, Hh, G3);
    bar_reset<<<1, 1>>>();
    gru_layer_ws<<<NBLK, NTHR, SMEM_BYTES>>>(xg, w_hh1, b_hh1, hT, y);

    // -------- final FC --------
    gemm_bias<<<dim3(Ii / 64, BT / 64), 256>>>(y, fcwT, fc_b, out, BT, Hh, Ii);
}

// round 9
// speedup vs baseline: 2.2422x; 1.1017x over previous
#include <cuda_runtime.h>
#include <cuda_fp16.h>
#include <math.h>

#define Bb 64
#define Tt 1024
#define Ii 64
#define Hh 512
#define G3 1536
#define BT (Bb*Tt)
#define NBLK 128
#define BH (Bb*Hh)

// SMEM byte offsets for the persistent kernel
#define OFF_HI   0                       // h_hi plane [64][520] halves
#define OFF_LO   66560                   // h_lo plane [64][520] halves
#define OFF_WF   133120                  // w fragments: 4096 uint2 = 32 KB
#define OFF_PART 165888                  // 64*12 f32 = 3 KB
#define OFF_OWN  168960                  // 64*4 f32 exact h
#define SMEM_TOTAL_B 169984

// ---------------- scratch (static device allocations only) ----------------
__device__ float g_xg[(size_t)BT * G3];
__device__ float g_y[(size_t)BT * Hh];
__device__ unsigned int g_h2[2 * BH];    // packed (lo<<16 | hi) fp16 pair, [b][hidden]
__device__ float g_wih0T[Ii * G3];
__device__ float g_wih1T[Hh * G3];
__device__ float g_fcwT[Hh * Ii];
__device__ unsigned int g_arrive;
__device__ unsigned int g_gen;

// ---------------- transpose: in[R][C] -> out[C][R] ----------------
__global__ void transpose_k(const float* __restrict__ in, float* __restrict__ out,
                            int R, int C) {
    __shared__ float tile[32][33];
    int c0 = blockIdx.x * 32, r0 = blockIdx.y * 32;
    int x = threadIdx.x, y = threadIdx.y;
#pragma unroll
    for (int j = 0; j < 32; j += 8)
        tile[y + j][x] = in[(size_t)(r0 + y + j) * C + c0 + x];
    __syncthreads();
#pragma unroll
    for (int j = 0; j < 32; j += 8)
        out[(size_t)(c0 + y + j) * R + r0 + x] = tile[x][y + j];
}

// ---------------- tiled GEMM: out[M][N] = X[M][K] @ Wt[K][N] + bias ----------------
__global__ void gemm_bias(const float* __restrict__ X, const float* __restrict__ Wt,
                          const float* __restrict__ bias, float* __restrict__ out,
                          int M, int K, int N) {
    __shared__ float As[16][64];
    __shared__ float Bs[16][64];
    int tid = threadIdx.x;
    int n0 = blockIdx.x * 64, m0 = blockIdx.y * 64;
    int tx = tid % 16, ty = tid / 16;
    int am = tid / 4, ak = (tid % 4) * 4;
    int bk = tid / 16, bn = (tid % 16) * 4;
    float acc[4][4];
#pragma unroll
    for (int i = 0; i < 4; i++)
#pragma unroll
        for (int j = 0; j < 4; j++) acc[i][j] = 0.f;

    for (int k0 = 0; k0 < K; k0 += 16) {
        float4 av = *(const float4*)&X[(size_t)(m0 + am) * K + k0 + ak];
        As[ak + 0][am] = av.x; As[ak + 1][am] = av.y;
        As[ak + 2][am] = av.z; As[ak + 3][am] = av.w;
        *(float4*)&Bs[bk][bn] = *(const float4*)&Wt[(size_t)(k0 + bk) * N + n0 + bn];
        __syncthreads();
#pragma unroll
        for (int k = 0; k < 16; k++) {
            float4 a = *(const float4*)&As[k][ty * 4];
            float4 b = *(const float4*)&Bs[k][tx * 4];
            acc[0][0] += a.x * b.x; acc[0][1] += a.x * b.y; acc[0][2] += a.x * b.z; acc[0][3] += a.x * b.w;
            acc[1][0] += a.y * b.x; acc[1][1] += a.y * b.y; acc[1][2] += a.y * b.z; acc[1][3] += a.y * b.w;
            acc[2][0] += a.z * b.x; acc[2][1] += a.z * b.y; acc[2][2] += a.z * b.z; acc[2][3] += a.z * b.w;
            acc[3][0] += a.w * b.x; acc[3][1] += a.w * b.y; acc[3][2] += a.w * b.z; acc[3][3] += a.w * b.w;
        }
        __syncthreads();
    }
    float4 bv = *(const float4*)&bias[n0 + tx * 4];
#pragma unroll
    for (int i = 0; i < 4; i++) {
        float4 o;
        o.x = acc[i][0] + bv.x; o.y = acc[i][1] + bv.y;
        o.z = acc[i][2] + bv.z; o.w = acc[i][3] + bv.w;
        *(float4*)&out[(size_t)(m0 + ty * 4 + i) * N + n0 + tx * 4] = o;
    }
}

// ---------------- grid barrier ----------------
__global__ void bar_reset() { g_arrive = 0u; g_gen = 0u; }

__device__ __forceinline__ void grid_barrier(unsigned int target) {
    __syncthreads();
    if (threadIdx.x == 0) {
        __threadfence();
        unsigned int a = atomicAdd(&g_arrive, 1u);
        if (a == NBLK - 1) {
            g_arrive = 0u;
            __threadfence();
            atomicExch(&g_gen, target);
        } else {
            while (*((volatile unsigned int*)&g_gen) < target) {}
            __threadfence();
        }
    }
    __syncthreads();
}

// ---------------- mma helpers ----------------
__device__ __forceinline__ void mma16816(float* c, unsigned a0, unsigned a1,
                                         unsigned a2, unsigned a3,
                                         unsigned b0, unsigned b1) {
    asm volatile(
        "mma.sync.aligned.m16n8k16.row.col.f32.f16.f16.f32 "
        "{%0,%1,%2,%3}, {%4,%5,%6,%7}, {%8,%9}, {%0,%1,%2,%3};"
        : "+f"(c[0]), "+f"(c[1]), "+f"(c[2]), "+f"(c[3])
        : "r"(a0), "r"(a1), "r"(a2), "r"(a3), "r"(b0), "r"(b1));
}

__device__ __forceinline__ void ldsm4(unsigned& r0, unsigned& r1, unsigned& r2,
                                      unsigned& r3, unsigned addr) {
    asm volatile("ldmatrix.sync.aligned.m8n8.x4.shared.b16 {%0,%1,%2,%3}, [%4];"
                 : "=r"(r0), "=r"(r1), "=r"(r2), "=r"(r3) : "r"(addr));
}

__device__ __forceinline__ unsigned pack2h(__half a, __half b) {
    return (unsigned)__half_as_ushort(a) | ((unsigned)__half_as_ushort(b) << 16);
}

// ---------------- persistent split-fp16 tensor-core GRU layer ----------------
// 128 blocks x 256 threads (8 warps). Block bid owns h-cols j0..j0+3.
// warp wid: mi = wid>>1 (m tile: rows mi*16..+16), ni = wid&1 (cols ni*8..+8 of 12).
__global__ void __launch_bounds__(256, 1)
gru_layer_mma(const float* __restrict__ xg, const float* __restrict__ whh,
              const float* __restrict__ bhh, unsigned int* __restrict__ h2,
              float* __restrict__ y) {
    extern __shared__ unsigned char smraw[];
    float* part = (float*)(smraw + OFF_PART);
    float* own  = (float*)(smraw + OFF_OWN);
    uint2* wf   = (uint2*)(smraw + OFF_WF);
    const unsigned smem_b = (unsigned)__cvta_generic_to_shared(smraw);

    const int tid = threadIdx.x, bid = blockIdx.x;
    const int j0 = bid * 4;
    const int lane = tid & 31, wid = tid >> 5;
    const int mi = wid >> 1, ni = wid & 1;

    // ---- one-time: W_hh fragments (hi/lo fp16, mma B-frag order) ----
    for (int q = tid; q < 4096; q += 256) {
        int l = q & 31, ps = (q >> 5) & 1, s = (q >> 6) & 31, nn = q >> 11;
        int c = nn * 8 + (l >> 2), t = l & 3;
        float e0 = 0.f, e1 = 0.f, e2 = 0.f, e3 = 0.f;
        if (c < 12) {
            int g = c >> 2, jj = c & 3;
            const float* wr = whh + (size_t)(g * Hh + j0 + jj) * Hh;
            int k = s * 16 + t * 2;
            e0 = wr[k]; e1 = wr[k + 1]; e2 = wr[k + 8]; e3 = wr[k + 9];
        }
        __half h0 = __float2half_rn(e0), h1 = __float2half_rn(e1);
        __half h2v = __float2half_rn(e2), h3 = __float2half_rn(e3);
        if (ps) {
            h0 = __float2half_rn(e0 - __half2float(h0));
            h1 = __float2half_rn(e1 - __half2float(h1));
            h2v = __float2half_rn(e2 - __half2float(h2v));
            h3 = __float2half_rn(e3 - __half2float(h3));
        }
        uint2 v; v.x = pack2h(h0, h1); v.y = pack2h(h2v, h3);
        wf[q] = v;
    }

    // zero h plane 0 + own exact-h
    for (int i = bid * 256 + tid; i < BH; i += NBLK * 256) h2[i] = 0u;
    own[tid] = 0.f;

    // hoisted per-thread constants for the update phase
    const int ub = tid >> 2, uj = tid & 3;
    const float bhr = bhh[j0 + uj];
    const float bhz = bhh[Hh + j0 + uj];
    const float bhn = bhh[2 * Hh + j0 + uj];
    const float* xp = xg + (size_t)ub * Tt * G3 + j0 + uj;
    float* yp = y + (size_t)ub * Tt * Hh + j0 + uj;

    // ldmatrix addresses (A tiles)
    const unsigned aoff = (unsigned)(((mi * 16 + (lane & 15)) * 520 + ((lane >> 4) * 8)) * 2);
    const unsigned a_hi = smem_b + OFF_HI + aoff;
    const unsigned a_lo = smem_b + OFF_LO + aoff;
    const unsigned bbase = smem_b + OFF_WF + (unsigned)(ni * 16384 + lane * 8);

    unsigned int bar = 0;
    grid_barrier(++bar);

    for (int t = 0; t < Tt; t++) {
        const uint4* hc4 = (const uint4*)(h2 + (t & 1) * BH);
        unsigned int* hnext = h2 + ((t + 1) & 1) * BH;

        // prefetch xg (DRAM) for the gate phase
        float xr = xp[(size_t)t * G3];
        float xz = xp[(size_t)t * G3 + Hh];
        float xn = xp[(size_t)t * G3 + 2 * Hh];

        // ---- stage h (hi/lo planes), coalesced ----
#pragma unroll
        for (int i = 0; i < 32; i++) {
            int idx = i * 256 + tid;
            int m = idx >> 7, kq = idx & 127;
            uint4 e = hc4[idx];
            unsigned hi0 = __byte_perm(e.x, e.y, 0x5410);
            unsigned lo0 = __byte_perm(e.x, e.y, 0x7632);
            unsigned hi1 = __byte_perm(e.z, e.w, 0x5410);
            unsigned lo1 = __byte_perm(e.z, e.w, 0x7632);
            unsigned doff = (unsigned)(m * 1040 + kq * 8);
            *(uint2*)(smraw + OFF_HI + doff) = make_uint2(hi0, hi1);
            *(uint2*)(smraw + OFF_LO + doff) = make_uint2(lo0, lo1);
        }
        __syncthreads();

        // ---- tensor-core GEMM: 3-term split-fp16 ----
        float chh[4] = {0.f, 0.f, 0.f, 0.f};
        float chl[4] = {0.f, 0.f, 0.f, 0.f};
        float clh[4] = {0.f, 0.f, 0.f, 0.f};
#pragma unroll
        for (int s = 0; s < 32; s++) {
            unsigned Ah0, Ah1, Ah2, Ah3, Al0, Al1, Al2, Al3;
            ldsm4(Ah0, Ah1, Ah2, Ah3, a_hi + s * 32);
            ldsm4(Al0, Al1, Al2, Al3, a_lo + s * 32);
            unsigned bh0, bh1, bl0, bl1;
            asm volatile("ld.shared.v2.u32 {%0,%1}, [%2];"
                         : "=r"(bh0), "=r"(bh1) : "r"(bbase + s * 512));
            asm volatile("ld.shared.v2.u32 {%0,%1}, [%2];"
                         : "=r"(bl0), "=r"(bl1) : "r"(bbase + s * 512 + 256));
            mma16816(chh, Ah0, Ah1, Ah2, Ah3, bh0, bh1);
            mma16816(chl, Ah0, Ah1, Ah2, Ah3, bl0, bl1);
            mma16816(clh, Al0, Al1, Al2, Al3, bh0, bh1);
        }
        {
            float d0 = chh[0] + chl[0] + clh[0];
            float d1 = chh[1] + chl[1] + clh[1];
            float d2 = chh[2] + chl[2] + clh[2];
            float d3 = chh[3] + chl[3] + clh[3];
            int r = lane >> 2, tc = (lane & 3) * 2;
            int b = mi * 16 + r;
            int c0 = ni * 8 + tc;
            if (c0 < 12) { part[b * 12 + c0] = d0; part[(b + 8) * 12 + c0] = d2; }
            if (c0 + 1 < 12) { part[b * 12 + c0 + 1] = d1; part[(b + 8) * 12 + c0 + 1] = d3; }
        }
        __syncthreads();

        // ---- gate update (all 256 threads: (b, j)) ----
        {
            float hr = bhr + part[ub * 12 + uj];
            float hz = bhz + part[ub * 12 + 4 + uj];
            float hn_ = bhn + part[ub * 12 + 8 + uj];
            float r = 1.f / (1.f + expf(-(xr + hr)));
            float z = 1.f / (1.f + expf(-(xz + hz)));
            float n = tanhf(xn + r * hn_);
            float hp = own[ub * 4 + uj];
            float v = (1.f - z) * n + z * hp;
            own[ub * 4 + uj] = v;
            __half vh = __float2half_rn(v);
            __half vl = __float2half_rn(v - __half2float(vh));
            hnext[ub * Hh + j0 + uj] = pack2h(vh, vl);
            yp[(size_t)t * Hh] = v;
        }
        grid_barrier(++bar);
    }
}

// ---------------- launch ----------------
extern "C" void kernel_launch(void* const* d_in, const int* in_sizes, int n_in,
                              void* d_out, int out_size) {
    const float* x     = (const float*)d_in[0];
    const float* w_ih0 = (const float*)d_in[1];
    const float* w_hh0 = (const float*)d_in[2];
    const float* b_ih0 = (const float*)d_in[3];
    const float* b_hh0 = (const float*)d_in[4];
    const float* w_ih1 = (const float*)d_in[5];
    const float* w_hh1 = (const float*)d_in[6];
    const float* b_ih1 = (const float*)d_in[7];
    const float* b_hh1 = (const float*)d_in[8];
    const float* fc_w  = (const float*)d_in[9];
    const float* fc_b  = (const float*)d_in[10];
    float* out = (float*)d_out;

    float *xg, *y, *wih0T, *wih1T, *fcwT;
    unsigned int* h2;
    cudaGetSymbolAddress((void**)&xg,    g_xg);
    cudaGetSymbolAddress((void**)&y,     g_y);
    cudaGetSymbolAddress((void**)&h2,    g_h2);
    cudaGetSymbolAddress((void**)&wih0T, g_wih0T);
    cudaGetSymbolAddress((void**)&wih1T, g_wih1T);
    cudaGetSymbolAddress((void**)&fcwT,  g_fcwT);

    cudaFuncSetAttribute(gru_layer_mma,
                         cudaFuncAttributeMaxDynamicSharedMemorySize, SMEM_TOTAL_B);

    dim3 tb(32, 8);
    transpose_k<<<dim3(Ii / 32, G3 / 32), tb>>>(w_ih0, wih0T, G3, Ii);
    transpose_k<<<dim3(Hh / 32, G3 / 32), tb>>>(w_ih1, wih1T, G3, Hh);
    transpose_k<<<dim3(Hh / 32, Ii / 32), tb>>>(fc_w,  fcwT,  Ii, Hh);

    // -------- layer 0 --------
    gemm_bias<<<dim3(G3 / 64, BT / 64), 256>>>(x, wih0T, b_ih0, xg, BT, Ii, G3);
    bar_reset<<<1, 1>>>();
    gru_layer_mma<<<NBLK, 256, SMEM_TOTAL_B>>>(xg, w_hh0, b_hh0, h2, y);

    // -------- layer 1 --------
    gemm_bias<<<dim3(G3 / 64, BT / 64), 256>>>(y, wih1T, b_ih1, xg, BT, Hh, G3);
    bar_reset<<<1, 1>>>();
    gru_layer_mma<<<NBLK, 256, SMEM_TOTAL_B>>>(xg, w_hh1, b_hh1, h2, y);

    // -------- final FC --------
    gemm_bias<<<dim3(Ii / 64, BT / 64), 256>>>(y, fcwT, fc_b, out, BT, Hh, Ii);
}